// round 15
// baseline (speedup 1.0000x reference)
#include <cuda_runtime.h>
#include <cuda_bf16.h>
#include <math.h>

#define BB 64
#define TT 512
#define FF 64
#define EE 256
#define HH 512
#define GG 2048   // 4*H
#define OO 128
#define NB 64     // persistent blocks, 8 hidden units (32 gate-cols) each

// ---------------- device scratch ----------------
__device__ float g_xg[(size_t)TT * NB * 32 * 64];    // [t][blk][c(32)][b(64)]
__device__ float g_Wc[GG * FF];
__device__ float g_biasc[GG];
__device__ unsigned short g_h16[2][2][64 * 512];     // [buf][hi|lo][b*512+k] bf16
__device__ float g_hsum[BB * HH];
struct BarCnt { unsigned v; unsigned pad[63]; };
__device__ BarCnt g_cnt[16];

// smem byte offsets (dynamic smem)
#define S_WHI 0u
#define S_WLO 33280u          // 32*1040
#define S_AHI 66560u
#define S_ALO 133120u         // +64*1040
#define S_RED 199680u         // float[64][36]
#define S_TOT 208896u

// ---------------- helpers ----------------
__device__ __forceinline__ void ffma2(unsigned long long& d, unsigned long long a,
                                      unsigned long long b) {
    asm("fma.rn.f32x2 %0, %1, %2, %3;" : "=l"(d) : "l"(a), "l"(b), "l"(d));
}
__device__ __forceinline__ unsigned long long dup2(float x) {
    unsigned long long r; unsigned u = __float_as_uint(x);
    asm("mov.b64 %0, {%1, %1};" : "=l"(r) : "r"(u));
    return r;
}
__device__ __forceinline__ float lo32(unsigned long long v) { return __uint_as_float((unsigned)v); }
__device__ __forceinline__ float hi32(unsigned long long v) { return __uint_as_float((unsigned)(v >> 32)); }

__device__ __forceinline__ unsigned smem_u32(const void* p) {
    unsigned a;
    asm("{ .reg .u64 t; cvta.to.shared.u64 t, %1; cvt.u32.u64 %0, t; }" : "=r"(a) : "l"(p));
    return a;
}
__device__ __forceinline__ void cpasync16s(unsigned dst, const void* src) {
    asm volatile("cp.async.cg.shared.global [%0], [%1], 16;" :: "r"(dst), "l"(src));
}
#define CP_COMMIT() asm volatile("cp.async.commit_group;")
#define CP_WAITN(n) asm volatile("cp.async.wait_group %0;" :: "n"(n))

__device__ __forceinline__ void ldsm_x4(unsigned& r0, unsigned& r1, unsigned& r2,
                                        unsigned& r3, unsigned addr) {
    asm volatile("ldmatrix.sync.aligned.m8n8.x4.shared.b16 {%0,%1,%2,%3}, [%4];"
                 : "=r"(r0), "=r"(r1), "=r"(r2), "=r"(r3) : "r"(addr));
}
__device__ __forceinline__ void mma16816(float d[4], unsigned a0, unsigned a1,
                                         unsigned a2, unsigned a3,
                                         unsigned b0, unsigned b1) {
    asm volatile("mma.sync.aligned.m16n8k16.row.col.f32.bf16.bf16.f32 "
                 "{%0,%1,%2,%3}, {%4,%5,%6,%7}, {%8,%9}, {%0,%1,%2,%3};"
                 : "+f"(d[0]), "+f"(d[1]), "+f"(d[2]), "+f"(d[3])
                 : "r"(a0), "r"(a1), "r"(a2), "r"(a3), "r"(b0), "r"(b1));
}

__device__ __forceinline__ float ftanh(float x) {
    x = fminf(fmaxf(x, -15.f), 15.f);
    float e = __expf(2.f * x);
    return (e - 1.f) / (e + 1.f);
}
__device__ __forceinline__ float fsig(float x) { return 1.f / (1.f + __expf(-x)); }

// ---------------- 1. fuse weights: Wc = W_ih @ W_emb ----------------
__global__ void fuse_weights_kernel(const float* __restrict__ Wih,
                                    const float* __restrict__ Wemb,
                                    const float* __restrict__ bemb,
                                    const float* __restrict__ bih,
                                    const float* __restrict__ bhh) {
    int g = blockIdx.x, f = threadIdx.x;
    __shared__ float s[EE];
    for (int e = f; e < EE; e += 64) s[e] = Wih[g * EE + e];
    __syncthreads();
    float acc = 0.f;
#pragma unroll 8
    for (int e = 0; e < EE; e++) acc += s[e] * Wemb[e * FF + f];
    g_Wc[g * FF + f] = acc;
    if (f == 0) {
        float bb = 0.f;
        for (int e = 0; e < EE; e++) bb += s[e] * bemb[e];
        g_biasc[g] = bb + bih[g] + bhh[g];
    }
}

// ---------------- 2. xg = x @ Wc^T + biasc, out [t][blk][c(32)][b] ----------
__global__ __launch_bounds__(256) void xg_kernel(const float* __restrict__ x) {
    __shared__ __align__(16) float xs[FF][68];
    __shared__ __align__(16) float ws[FF][68];
    int tb = blockIdx.x, cbase = blockIdx.y * 64, tid = threadIdx.x;
#pragma unroll
    for (int i = 0; i < 16; i++) {
        int idx = i * 256 + tid;
        int r = idx >> 6, k = idx & 63;
        xs[k][r] = x[((size_t)r * TT + tb) * FF + k];
        ws[k][r] = g_Wc[(size_t)(cbase + r) * FF + k];
    }
    __syncthreads();
    int rg = tid & 15, cg = tid >> 4;
    int r0 = rg * 4, c0 = cg * 4;
    unsigned long long acc[4][2] = {};
#pragma unroll 4
    for (int k = 0; k < FF; k++) {
        float4 hv = *(const float4*)&xs[k][r0];
        ulonglong2 wv = *(const ulonglong2*)&ws[k][c0];
        unsigned long long h0 = dup2(hv.x), h1 = dup2(hv.y), h2 = dup2(hv.z), h3 = dup2(hv.w);
        ffma2(acc[0][0], h0, wv.x); ffma2(acc[0][1], h0, wv.y);
        ffma2(acc[1][0], h1, wv.x); ffma2(acc[1][1], h1, wv.y);
        ffma2(acc[2][0], h2, wv.x); ffma2(acc[2][1], h2, wv.y);
        ffma2(acc[3][0], h3, wv.x); ffma2(acc[3][1], h3, wv.y);
    }
#pragma unroll
    for (int j = 0; j < 4; j++) {
        int g = cbase + c0 + j;
        float bias = g_biasc[g];
        int blk = (g & 511) >> 3;
        int cc = ((g >> 9) << 3) + (g & 7);
        float4 v;
        v.x = ((j & 1) ? hi32(acc[0][j >> 1]) : lo32(acc[0][j >> 1])) + bias;
        v.y = ((j & 1) ? hi32(acc[1][j >> 1]) : lo32(acc[1][j >> 1])) + bias;
        v.z = ((j & 1) ? hi32(acc[2][j >> 1]) : lo32(acc[2][j >> 1])) + bias;
        v.w = ((j & 1) ? hi32(acc[3][j >> 1]) : lo32(acc[3][j >> 1])) + bias;
        *(float4*)&g_xg[((((size_t)tb * NB + blk) * 32 + cc) << 6) + r0] = v;
    }
}

// ---------------- 3. init ----------------
__global__ void init_state_kernel() {
    int i = blockIdx.x * 256 + threadIdx.x;
    if (i < 8192) ((uint4*)g_h16[0])[i] = make_uint4(0, 0, 0, 0);
    if (i < 16) g_cnt[i].v = 0u;
}

// ---------------- 4. persistent LSTM via mma.sync, 64 blocks x N=32 ----------
// 8 warps: mt=wid>>1 (16 batch rows), nt=wid&1 (16 gate-cols). bf16 3-term split.
__global__ __launch_bounds__(256, 1) void lstm_mma(const float* __restrict__ Whh) {
    extern __shared__ __align__(16) unsigned char smem[];
    unsigned sb = smem_u32(smem);
    float* red = (float*)(smem + S_RED);

    int tid = threadIdx.x, wid = tid >> 5, lane = tid & 31;
    int blk = blockIdx.x, j0 = blk * 8;
    int mt = wid >> 1, nt = wid & 1;

    // one-time W conversion: n = gate*8+jj (32 rows), K-major, stride 1040B
    for (int idx = tid; idx < 32 * 512; idx += 256) {
        int k = idx & 511, n = idx >> 9;
        float w = Whh[(size_t)((n >> 3) * 512 + j0 + (n & 7)) * 512 + k];
        __nv_bfloat16 hb = __float2bfloat16(w);
        __nv_bfloat16 lb = __float2bfloat16(w - __bfloat162float(hb));
        *(unsigned short*)(smem + S_WHI + n * 1040 + k * 2) = *(unsigned short*)&hb;
        *(unsigned short*)(smem + S_WLO + n * 1040 + k * 2) = *(unsigned short*)&lb;
    }
    __syncthreads();

    // lane-fixed ldmatrix bases
    int q = lane >> 3, r8 = lane & 7;
    // A x4: m0:[rows mt16+r8,k0] m1:[+8,k0] m2:[r8,k8] m3:[+8,k8]
    unsigned aBase = sb + S_AHI + (unsigned)((mt * 16 + (q & 1) * 8 + r8) * 1040
                                             + ((q >> 1) * 8) * 2);
    // B x4: m0:[n nt16+r8,k0] m1:[same,k8] m2:[+8,k0] m3:[+8,k8]
    unsigned bBase = sb + S_WHI + (unsigned)((nt * 16 + (q >> 1) * 8 + r8) * 1040
                                             + ((q & 1) * 8) * 2);
    // epilogue mapping: thread -> (b, jj) and (b, jj+4)
    int eb = tid & 63, ejj = tid >> 6;

    float c_reg[2] = {0.f, 0.f}, hsum_reg[2] = {0.f, 0.f};

    for (int t = 0; t < TT; t++) {
        // xg prefetch: 4 gates x 2 jj
        const float* xp = g_xg + ((((size_t)t * NB + blk) * 32) << 6) + eb;
        float xv[8];
#pragma unroll
        for (int gte = 0; gte < 4; gte++) {
            xv[gte]     = __ldcg(xp + (gte * 8 + ejj) * 64);
            xv[4 + gte] = __ldcg(xp + (gte * 8 + ejj + 4) * 64);
        }

        // warp loads its own 8 A rows (mt*16 + nt*8 ..+8), hi+lo, 4 k-chunks
        const unsigned short* himg0 = g_h16[t & 1][0];
        const unsigned short* himg1 = g_h16[t & 1][1];
        int rbase = mt * 16 + nt * 8;
#pragma unroll
        for (int g = 0; g < 4; g++) {
#pragma unroll
            for (int i = 0; i < 8; i++) {
                int e = i * 32 + lane;                  // 0..255
                int prec = e >> 7, e2 = e & 127;
                int row = rbase + (e2 >> 4), kseg = g * 16 + (e2 & 15);
                const unsigned short* src = (prec ? himg1 : himg0) + row * 512 + kseg * 8;
                cpasync16s(sb + S_AHI + prec * 66560u + row * 1040u + kseg * 16u, src);
            }
            CP_COMMIT();
        }

        float d0[4] = {0.f, 0.f, 0.f, 0.f};
        float d1[4] = {0.f, 0.f, 0.f, 0.f};

#define CHUNK(KC, WN)                                                          \
        CP_WAITN(WN);                                                          \
        asm volatile("bar.sync %0, 64;" :: "r"(1 + mt) : "memory");            \
        {                                                                      \
            _Pragma("unroll")                                                  \
            for (int s = 0; s < 8; s++) {                                      \
                unsigned koff = (unsigned)(((KC) * 128 + s * 16) * 2);         \
                unsigned ah0, ah1, ah2, ah3, al0, al1, al2, al3;               \
                unsigned bh0, bh1, bh2, bh3, bl0, bl1, bl2, bl3;               \
                ldsm_x4(ah0, ah1, ah2, ah3, aBase + koff);                     \
                ldsm_x4(al0, al1, al2, al3, aBase + 66560u + koff);            \
                ldsm_x4(bh0, bh1, bh2, bh3, bBase + koff);                     \
                ldsm_x4(bl0, bl1, bl2, bl3, bBase + 33280u + koff);            \
                mma16816(d0, ah0, ah1, ah2, ah3, bh0, bh1);                    \
                mma16816(d0, al0, al1, al2, al3, bh0, bh1);                    \
                mma16816(d0, ah0, ah1, ah2, ah3, bl0, bl1);                    \
                mma16816(d1, ah0, ah1, ah2, ah3, bh2, bh3);                    \
                mma16816(d1, al0, al1, al2, al3, bh2, bh3);                    \
                mma16816(d1, ah0, ah1, ah2, ah3, bl2, bl3);                    \
            }                                                                  \
        }
        CHUNK(0, 3)
        CHUNK(1, 2)
        CHUNK(2, 1)
        CHUNK(3, 0)
#undef CHUNK

        // D frags -> red[b][c] (stride 36 floats)
        {
            int rr = lane >> 2, cc = (lane & 3) * 2;
            *(float2*)&red[(mt * 16 + rr) * 36 + nt * 16 + cc]      = make_float2(d0[0], d0[1]);
            *(float2*)&red[(mt * 16 + 8 + rr) * 36 + nt * 16 + cc]  = make_float2(d0[2], d0[3]);
            *(float2*)&red[(mt * 16 + rr) * 36 + nt * 16 + 8 + cc]     = make_float2(d1[0], d1[1]);
            *(float2*)&red[(mt * 16 + 8 + rr) * 36 + nt * 16 + 8 + cc] = make_float2(d1[2], d1[3]);
        }
        __syncthreads();

        // epilogue: thread handles (eb, ejj) and (eb, ejj+4)
        {
            const float* rr = &red[eb * 36];
            int nbuf = (t + 1) & 1;
#pragma unroll
            for (int u = 0; u < 2; u++) {
                int jj = ejj + u * 4;
                float iv = fsig(rr[jj]      + xv[u * 4 + 0]);
                float fv = fsig(rr[8 + jj]  + xv[u * 4 + 1]);
                float gv = ftanh(rr[16 + jj] + xv[u * 4 + 2]);
                float ov = fsig(rr[24 + jj] + xv[u * 4 + 3]);
                c_reg[u] = fv * c_reg[u] + iv * gv;
                float hn = ov * ftanh(c_reg[u]);
                hsum_reg[u] += hn;
                __nv_bfloat16 hb = __float2bfloat16(hn);
                __nv_bfloat16 lb = __float2bfloat16(hn - __bfloat162float(hb));
                g_h16[nbuf][0][eb * 512 + j0 + jj] = *(unsigned short*)&hb;
                g_h16[nbuf][1][eb * 512 + j0 + jj] = *(unsigned short*)&lb;
            }
        }

        // grid barrier (R9 verbatim, 64 arrivals)
        if (t < TT - 1) {
            __threadfence();
            __syncthreads();
            if (tid == 0) atomicAdd(&g_cnt[blk & 15].v, 1u);
            if (tid < 16) {
                unsigned want = 4u * (unsigned)(t + 1);
                while (*(volatile unsigned*)&g_cnt[tid].v < want) { }
            }
            __syncthreads();
            __threadfence();
        }
    }
    g_hsum[eb * HH + j0 + ejj]     = hsum_reg[0];
    g_hsum[eb * HH + j0 + ejj + 4] = hsum_reg[1];
}

// ---------------- 5. pool + FC ----------------
__global__ void pool_fc_kernel(const float* __restrict__ Wfc,
                               const float* __restrict__ bfc,
                               float* __restrict__ out) {
    int b = blockIdx.x;
    __shared__ float sh[HH];
    int tid = threadIdx.x;
    for (int k = tid; k < HH; k += 256) sh[k] = g_hsum[b * HH + k];
    __syncthreads();
    int warp = tid >> 5, lane = tid & 31;
    for (int o = warp; o < OO; o += 8) {
        float a = 0.f;
        for (int k = lane; k < HH; k += 32) a += sh[k] * Wfc[o * HH + k];
#pragma unroll
        for (int s = 16; s; s >>= 1) a += __shfl_xor_sync(0xffffffffu, a, s);
        if (lane == 0) out[b * OO + o] = a * (1.f / 512.f) + bfc[o];
    }
}

extern "C" void kernel_launch(void* const* d_in, const int* in_sizes, int n_in,
                              void* d_out, int out_size) {
    const float* x    = (const float*)d_in[0];
    const float* Wemb = (const float*)d_in[1];
    const float* bemb = (const float*)d_in[2];
    const float* Wih  = (const float*)d_in[3];
    const float* Whh  = (const float*)d_in[4];
    const float* bih  = (const float*)d_in[5];
    const float* bhh  = (const float*)d_in[6];
    const float* Wfc  = (const float*)d_in[7];
    const float* bfc  = (const float*)d_in[8];
    float* out = (float*)d_out;

    static bool attr_set = false;
    if (!attr_set) {
        cudaFuncSetAttribute(lstm_mma, cudaFuncAttributeMaxDynamicSharedMemorySize, S_TOT);
        attr_set = true;
    }

    fuse_weights_kernel<<<GG, 64>>>(Wih, Wemb, bemb, bih, bhh);

    dim3 xgrid(TT, GG / 64);
    xg_kernel<<<xgrid, 256>>>(x);

    init_state_kernel<<<32, 256>>>();

    lstm_mma<<<NB, 256, S_TOT>>>(Whh);

    pool_fc_kernel<<<BB, 256>>>(Wfc, bfc, out);
}

// round 16
// speedup vs baseline: 1.2273x; 1.2273x over previous
#include <cuda_runtime.h>
#include <cuda_bf16.h>
#include <math.h>

#define BB 64
#define TT 512
#define FF 64
#define EE 256
#define HH 512
#define GG 2048   // 4*H
#define OO 128
#define NBLK 128  // 2 batch-halves x 64 j-groups (8 hidden units each)

// ---------------- device scratch ----------------
__device__ float g_xg[(size_t)TT * NBLK * 32 * 32];  // [t][blk][c(32)][b(32)]
__device__ float g_Wc[GG * FF];
__device__ float g_biasc[GG];
__device__ unsigned short g_h16[2][2][64 * 512];     // [buf][hi|lo][b*512+k] bf16
__device__ float g_hsum[BB * HH];
struct BarCnt { unsigned v; unsigned pad[63]; };
__device__ BarCnt g_cnt[16];

// smem byte offsets (dynamic smem)
#define S_WHI 0u
#define S_WLO 33280u          // 32 rows * 1040B
#define S_AHI 66560u
#define S_ALO 99840u          // +32*1040
#define S_RED 133120u         // float[32][36]
#define S_TOT 137728u

// ---------------- helpers ----------------
__device__ __forceinline__ void ffma2(unsigned long long& d, unsigned long long a,
                                      unsigned long long b) {
    asm("fma.rn.f32x2 %0, %1, %2, %3;" : "=l"(d) : "l"(a), "l"(b), "l"(d));
}
__device__ __forceinline__ unsigned long long dup2(float x) {
    unsigned long long r; unsigned u = __float_as_uint(x);
    asm("mov.b64 %0, {%1, %1};" : "=l"(r) : "r"(u));
    return r;
}
__device__ __forceinline__ float lo32(unsigned long long v) { return __uint_as_float((unsigned)v); }
__device__ __forceinline__ float hi32(unsigned long long v) { return __uint_as_float((unsigned)(v >> 32)); }

__device__ __forceinline__ unsigned smem_u32(const void* p) {
    unsigned a;
    asm("{ .reg .u64 t; cvta.to.shared.u64 t, %1; cvt.u32.u64 %0, t; }" : "=r"(a) : "l"(p));
    return a;
}
__device__ __forceinline__ void cpasync16s(unsigned dst, const void* src) {
    asm volatile("cp.async.cg.shared.global [%0], [%1], 16;" :: "r"(dst), "l"(src));
}
#define CP_COMMIT() asm volatile("cp.async.commit_group;")
#define CP_WAITN(n) asm volatile("cp.async.wait_group %0;" :: "n"(n))

__device__ __forceinline__ void ldsm_x4(unsigned& r0, unsigned& r1, unsigned& r2,
                                        unsigned& r3, unsigned addr) {
    asm volatile("ldmatrix.sync.aligned.m8n8.x4.shared.b16 {%0,%1,%2,%3}, [%4];"
                 : "=r"(r0), "=r"(r1), "=r"(r2), "=r"(r3) : "r"(addr));
}
__device__ __forceinline__ void ldsm_x2(unsigned& r0, unsigned& r1, unsigned addr) {
    asm volatile("ldmatrix.sync.aligned.m8n8.x2.shared.b16 {%0,%1}, [%2];"
                 : "=r"(r0), "=r"(r1) : "r"(addr));
}
__device__ __forceinline__ void mma16816(float d[4], unsigned a0, unsigned a1,
                                         unsigned a2, unsigned a3,
                                         unsigned b0, unsigned b1) {
    asm volatile("mma.sync.aligned.m16n8k16.row.col.f32.bf16.bf16.f32 "
                 "{%0,%1,%2,%3}, {%4,%5,%6,%7}, {%8,%9}, {%0,%1,%2,%3};"
                 : "+f"(d[0]), "+f"(d[1]), "+f"(d[2]), "+f"(d[3])
                 : "r"(a0), "r"(a1), "r"(a2), "r"(a3), "r"(b0), "r"(b1));
}

__device__ __forceinline__ float ftanh(float x) {
    x = fminf(fmaxf(x, -15.f), 15.f);
    float e = __expf(2.f * x);
    return (e - 1.f) / (e + 1.f);
}
__device__ __forceinline__ float fsig(float x) { return 1.f / (1.f + __expf(-x)); }

// ---------------- 1. fuse weights: Wc = W_ih @ W_emb ----------------
__global__ void fuse_weights_kernel(const float* __restrict__ Wih,
                                    const float* __restrict__ Wemb,
                                    const float* __restrict__ bemb,
                                    const float* __restrict__ bih,
                                    const float* __restrict__ bhh) {
    int g = blockIdx.x, f = threadIdx.x;
    __shared__ float s[EE];
    for (int e = f; e < EE; e += 64) s[e] = Wih[g * EE + e];
    __syncthreads();
    float acc = 0.f;
#pragma unroll 8
    for (int e = 0; e < EE; e++) acc += s[e] * Wemb[e * FF + f];
    g_Wc[g * FF + f] = acc;
    if (f == 0) {
        float bb = 0.f;
        for (int e = 0; e < EE; e++) bb += s[e] * bemb[e];
        g_biasc[g] = bb + bih[g] + bhh[g];
    }
}

// ---------------- 2. xg = x @ Wc^T + biasc, out [t][blk][c(32)][b(32)] -------
__global__ __launch_bounds__(256) void xg_kernel(const float* __restrict__ x) {
    __shared__ __align__(16) float xs[FF][68];
    __shared__ __align__(16) float ws[FF][68];
    int tb = blockIdx.x, cbase = blockIdx.y * 64, tid = threadIdx.x;
#pragma unroll
    for (int i = 0; i < 16; i++) {
        int idx = i * 256 + tid;
        int r = idx >> 6, k = idx & 63;
        xs[k][r] = x[((size_t)r * TT + tb) * FF + k];
        ws[k][r] = g_Wc[(size_t)(cbase + r) * FF + k];
    }
    __syncthreads();
    int rg = tid & 15, cg = tid >> 4;
    int r0 = rg * 4, c0 = cg * 4;
    unsigned long long acc[4][2] = {};
#pragma unroll 4
    for (int k = 0; k < FF; k++) {
        float4 hv = *(const float4*)&xs[k][r0];
        ulonglong2 wv = *(const ulonglong2*)&ws[k][c0];
        unsigned long long h0 = dup2(hv.x), h1 = dup2(hv.y), h2 = dup2(hv.z), h3 = dup2(hv.w);
        ffma2(acc[0][0], h0, wv.x); ffma2(acc[0][1], h0, wv.y);
        ffma2(acc[1][0], h1, wv.x); ffma2(acc[1][1], h1, wv.y);
        ffma2(acc[2][0], h2, wv.x); ffma2(acc[2][1], h2, wv.y);
        ffma2(acc[3][0], h3, wv.x); ffma2(acc[3][1], h3, wv.y);
    }
    int halfb = r0 >> 5;                      // batch half (float4 stays inside)
#pragma unroll
    for (int j = 0; j < 4; j++) {
        int g = cbase + c0 + j;
        float bias = g_biasc[g];
        int blk = halfb * 64 + ((g & 511) >> 3);
        int cc = ((g >> 9) << 3) + (g & 7);
        float4 v;
        v.x = ((j & 1) ? hi32(acc[0][j >> 1]) : lo32(acc[0][j >> 1])) + bias;
        v.y = ((j & 1) ? hi32(acc[1][j >> 1]) : lo32(acc[1][j >> 1])) + bias;
        v.z = ((j & 1) ? hi32(acc[2][j >> 1]) : lo32(acc[2][j >> 1])) + bias;
        v.w = ((j & 1) ? hi32(acc[3][j >> 1]) : lo32(acc[3][j >> 1])) + bias;
        *(float4*)&g_xg[((((size_t)tb * NBLK + blk) * 32 + cc) << 5) + (r0 & 31)] = v;
    }
}

// ---------------- 3. init ----------------
__global__ void init_state_kernel() {
    int i = blockIdx.x * 256 + threadIdx.x;
    if (i < 8192) ((uint4*)g_h16[0])[i] = make_uint4(0, 0, 0, 0);
    if (i < 16) g_cnt[i].v = 0u;
}

// ---------------- 4. persistent LSTM via mma.sync, 2-D split ------------------
// 128 blocks x 256 threads. Block (bg = blk>>6, jg = blk&63): 32 batches x 8 units.
// 8 warps: mt = wid>>2 (16 batch rows), nt = wid&3 (8 gate-cols). bf16 3-term.
__global__ __launch_bounds__(256, 1) void lstm_mma(const float* __restrict__ Whh) {
    extern __shared__ __align__(16) unsigned char smem[];
    unsigned sb = smem_u32(smem);
    float* red = (float*)(smem + S_RED);

    int tid = threadIdx.x, wid = tid >> 5, lane = tid & 31;
    int blk = blockIdx.x;
    int bg = blk >> 6, jg = blk & 63;
    int j0 = jg * 8, b0 = bg * 32;
    int mt = wid >> 2, nt = wid & 3;

    // one-time W conversion: n = gate*8+jj (32 rows), K-major, stride 1040B
    for (int idx = tid; idx < 32 * 512; idx += 256) {
        int k = idx & 511, n = idx >> 9;
        float w = Whh[(size_t)((n >> 3) * 512 + j0 + (n & 7)) * 512 + k];
        __nv_bfloat16 hb = __float2bfloat16(w);
        __nv_bfloat16 lb = __float2bfloat16(w - __bfloat162float(hb));
        *(unsigned short*)(smem + S_WHI + n * 1040 + k * 2) = *(unsigned short*)&hb;
        *(unsigned short*)(smem + S_WLO + n * 1040 + k * 2) = *(unsigned short*)&lb;
    }
    __syncthreads();

    // lane-fixed ldmatrix bases (identical frag layout to R14)
    int q = lane >> 3, r8 = lane & 7;
    unsigned aBase = sb + S_AHI + (unsigned)((mt * 16 + (q & 1) * 8 + r8) * 1040
                                             + ((q >> 1) * 8) * 2);
    unsigned bBase = sb + S_WHI + (unsigned)((nt * 8 + r8) * 1040
                                             + (((lane >> 3) & 1) * 8) * 2);
    // epilogue mapping: one thread per (local batch, jj)
    int eb = tid & 31, ejj = tid >> 5;

    float c_reg = 0.f, hsum_reg = 0.f;

    for (int t = 0; t < TT; t++) {
        // xg prefetch (4 gates for this (b,jj))
        const float* xp = g_xg + ((((size_t)t * NBLK + blk) * 32) << 5) + eb;
        float xv0 = __ldcg(xp + (ejj) * 32);
        float xv1 = __ldcg(xp + (8 + ejj) * 32);
        float xv2 = __ldcg(xp + (16 + ejj) * 32);
        float xv3 = __ldcg(xp + (24 + ejj) * 32);

        // A loads: warp wid owns local rows [wid*4, wid*4+4), hi+lo, 2 k-chunks
        const unsigned short* himg0 = g_h16[t & 1][0];
        const unsigned short* himg1 = g_h16[t & 1][1];
        int rbase = wid * 4;
#pragma unroll
        for (int g = 0; g < 2; g++) {
#pragma unroll
            for (int i = 0; i < 8; i++) {
                int e = i * 32 + lane;                 // 0..255
                int prec = e >> 7, e2 = e & 127;       // row(4) x kseg(32)
                int row = rbase + (e2 >> 5), kidx = e2 & 31;
                const unsigned short* src = (prec ? himg1 : himg0)
                                          + (b0 + row) * 512 + (g * 32 + kidx) * 8;
                cpasync16s(sb + S_AHI + prec * 33280u + row * 1040u
                           + (unsigned)(g * 32 + kidx) * 16u, src);
            }
            CP_COMMIT();
        }

        float d[4] = {0.f, 0.f, 0.f, 0.f};

#define CHUNK(KC, WN)                                                          \
        CP_WAITN(WN);                                                          \
        asm volatile("bar.sync %0, 128;" :: "r"(1 + mt) : "memory");           \
        {                                                                      \
            _Pragma("unroll")                                                  \
            for (int s = 0; s < 16; s++) {                                     \
                unsigned koff = (unsigned)(((KC) * 256 + s * 16) * 2);         \
                unsigned ah0, ah1, ah2, ah3, al0, al1, al2, al3;               \
                unsigned bh0, bh1, bl0, bl1;                                   \
                ldsm_x4(ah0, ah1, ah2, ah3, aBase + koff);                     \
                ldsm_x4(al0, al1, al2, al3, aBase + 33280u + koff);            \
                ldsm_x2(bh0, bh1, bBase + koff);                               \
                ldsm_x2(bl0, bl1, bBase + 33280u + koff);                      \
                mma16816(d, ah0, ah1, ah2, ah3, bh0, bh1);                     \
                mma16816(d, al0, al1, al2, al3, bh0, bh1);                     \
                mma16816(d, ah0, ah1, ah2, ah3, bl0, bl1);                     \
            }                                                                  \
        }
        CHUNK(0, 1)
        CHUNK(1, 0)
#undef CHUNK

        // D frags -> red[b][c] (stride 36 floats)
        {
            int rr = lane >> 2, cc = (lane & 3) * 2;
            *(float2*)&red[(mt * 16 + rr) * 36 + nt * 8 + cc]     = make_float2(d[0], d[1]);
            *(float2*)&red[(mt * 16 + 8 + rr) * 36 + nt * 8 + cc] = make_float2(d[2], d[3]);
        }
        __syncthreads();

        // epilogue: thread (eb, ejj)
        {
            const float* rr = &red[eb * 36];
            float iv = fsig(rr[ejj]      + xv0);
            float fv = fsig(rr[8 + ejj]  + xv1);
            float gv = ftanh(rr[16 + ejj] + xv2);
            float ov = fsig(rr[24 + ejj] + xv3);
            c_reg = fv * c_reg + iv * gv;
            float hn = ov * ftanh(c_reg);
            hsum_reg += hn;
            __nv_bfloat16 hb = __float2bfloat16(hn);
            __nv_bfloat16 lb = __float2bfloat16(hn - __bfloat162float(hb));
            int nbuf = (t + 1) & 1;
            g_h16[nbuf][0][(b0 + eb) * 512 + j0 + ejj] = *(unsigned short*)&hb;
            g_h16[nbuf][1][(b0 + eb) * 512 + j0 + ejj] = *(unsigned short*)&lb;
        }

        // grid barrier (R9 verbatim, 128 arrivals over 16 counters)
        if (t < TT - 1) {
            __threadfence();
            __syncthreads();
            if (tid == 0) atomicAdd(&g_cnt[blk & 15].v, 1u);
            if (tid < 16) {
                unsigned want = 8u * (unsigned)(t + 1);
                while (*(volatile unsigned*)&g_cnt[tid].v < want) { }
            }
            __syncthreads();
            __threadfence();
        }
    }
    g_hsum[(b0 + eb) * HH + j0 + ejj] = hsum_reg;
}

// ---------------- 5. pool + FC ----------------
__global__ void pool_fc_kernel(const float* __restrict__ Wfc,
                               const float* __restrict__ bfc,
                               float* __restrict__ out) {
    int b = blockIdx.x;
    __shared__ float sh[HH];
    int tid = threadIdx.x;
    for (int k = tid; k < HH; k += 256) sh[k] = g_hsum[b * HH + k];
    __syncthreads();
    int warp = tid >> 5, lane = tid & 31;
    for (int o = warp; o < OO; o += 8) {
        float a = 0.f;
        for (int k = lane; k < HH; k += 32) a += sh[k] * Wfc[o * HH + k];
#pragma unroll
        for (int s = 16; s; s >>= 1) a += __shfl_xor_sync(0xffffffffu, a, s);
        if (lane == 0) out[b * OO + o] = a * (1.f / 512.f) + bfc[o];
    }
}

extern "C" void kernel_launch(void* const* d_in, const int* in_sizes, int n_in,
                              void* d_out, int out_size) {
    const float* x    = (const float*)d_in[0];
    const float* Wemb = (const float*)d_in[1];
    const float* bemb = (const float*)d_in[2];
    const float* Wih  = (const float*)d_in[3];
    const float* Whh  = (const float*)d_in[4];
    const float* bih  = (const float*)d_in[5];
    const float* bhh  = (const float*)d_in[6];
    const float* Wfc  = (const float*)d_in[7];
    const float* bfc  = (const float*)d_in[8];
    float* out = (float*)d_out;

    static bool attr_set = false;
    if (!attr_set) {
        cudaFuncSetAttribute(lstm_mma, cudaFuncAttributeMaxDynamicSharedMemorySize, S_TOT);
        attr_set = true;
    }

    fuse_weights_kernel<<<GG, 64>>>(Wih, Wemb, bemb, bih, bhh);

    dim3 xgrid(TT, GG / 64);
    xg_kernel<<<xgrid, 256>>>(x);

    init_state_kernel<<<32, 256>>>();

    lstm_mma<<<NBLK, 256, S_TOT>>>(Whh);

    pool_fc_kernel<<<BB, 256>>>(Wfc, bfc, out);
}

// round 17
// speedup vs baseline: 1.4024x; 1.1426x over previous
#include <cuda_runtime.h>
#include <cuda_bf16.h>
#include <math.h>

#define BB 64
#define TT 512
#define FF 64
#define EE 256
#define HH 512
#define GG 2048   // 4*H
#define OO 128
#define NBLK 128  // 2 batch-halves x 64 j-groups (8 hidden units each)

// ---------------- device scratch ----------------
__device__ float g_xg[(size_t)TT * NBLK * 32 * 32];  // [t][blk][c(32)][b(32)], c = jj*4+gate
__device__ float g_Wc[GG * FF];
__device__ float g_biasc[GG];
__device__ unsigned short g_h16[2][2][64 * 512];     // [buf][hi|lo][b*512+k] bf16
__device__ float g_hsum[BB * HH];
struct BarCnt { unsigned v; unsigned pad[63]; };
__device__ BarCnt g_cnt[16];                         // [half*8 + idx]

// smem byte offsets (dynamic smem)
#define S_WHI 0u
#define S_WLO 33280u          // 32 rows * 1040B
#define S_AHI 66560u
#define S_ALO 99840u          // +32*1040
#define S_TOT 133120u

// ---------------- helpers ----------------
__device__ __forceinline__ void ffma2(unsigned long long& d, unsigned long long a,
                                      unsigned long long b) {
    asm("fma.rn.f32x2 %0, %1, %2, %3;" : "=l"(d) : "l"(a), "l"(b), "l"(d));
}
__device__ __forceinline__ unsigned long long dup2(float x) {
    unsigned long long r; unsigned u = __float_as_uint(x);
    asm("mov.b64 %0, {%1, %1};" : "=l"(r) : "r"(u));
    return r;
}
__device__ __forceinline__ float lo32(unsigned long long v) { return __uint_as_float((unsigned)v); }
__device__ __forceinline__ float hi32(unsigned long long v) { return __uint_as_float((unsigned)(v >> 32)); }

__device__ __forceinline__ unsigned smem_u32(const void* p) {
    unsigned a;
    asm("{ .reg .u64 t; cvta.to.shared.u64 t, %1; cvt.u32.u64 %0, t; }" : "=r"(a) : "l"(p));
    return a;
}
__device__ __forceinline__ void cpasync16s(unsigned dst, const void* src) {
    asm volatile("cp.async.cg.shared.global [%0], [%1], 16;" :: "r"(dst), "l"(src));
}
#define CP_COMMIT() asm volatile("cp.async.commit_group;")
#define CP_WAITN(n) asm volatile("cp.async.wait_group %0;" :: "n"(n))

__device__ __forceinline__ void ldsm_x4(unsigned& r0, unsigned& r1, unsigned& r2,
                                        unsigned& r3, unsigned addr) {
    asm volatile("ldmatrix.sync.aligned.m8n8.x4.shared.b16 {%0,%1,%2,%3}, [%4];"
                 : "=r"(r0), "=r"(r1), "=r"(r2), "=r"(r3) : "r"(addr));
}
__device__ __forceinline__ void ldsm_x2(unsigned& r0, unsigned& r1, unsigned addr) {
    asm volatile("ldmatrix.sync.aligned.m8n8.x2.shared.b16 {%0,%1}, [%2];"
                 : "=r"(r0), "=r"(r1) : "r"(addr));
}
__device__ __forceinline__ void mma16816(float d[4], unsigned a0, unsigned a1,
                                         unsigned a2, unsigned a3,
                                         unsigned b0, unsigned b1) {
    asm volatile("mma.sync.aligned.m16n8k16.row.col.f32.bf16.bf16.f32 "
                 "{%0,%1,%2,%3}, {%4,%5,%6,%7}, {%8,%9}, {%0,%1,%2,%3};"
                 : "+f"(d[0]), "+f"(d[1]), "+f"(d[2]), "+f"(d[3])
                 : "r"(a0), "r"(a1), "r"(a2), "r"(a3), "r"(b0), "r"(b1));
}

__device__ __forceinline__ float ftanh(float x) {
    x = fminf(fmaxf(x, -15.f), 15.f);
    float e = __expf(2.f * x);
    return (e - 1.f) / (e + 1.f);
}
__device__ __forceinline__ float fsig(float x) { return 1.f / (1.f + __expf(-x)); }

// ---------------- 1. fuse weights: Wc = W_ih @ W_emb ----------------
__global__ void fuse_weights_kernel(const float* __restrict__ Wih,
                                    const float* __restrict__ Wemb,
                                    const float* __restrict__ bemb,
                                    const float* __restrict__ bih,
                                    const float* __restrict__ bhh) {
    int g = blockIdx.x, f = threadIdx.x;
    __shared__ float s[EE];
    for (int e = f; e < EE; e += 64) s[e] = Wih[g * EE + e];
    __syncthreads();
    float acc = 0.f;
#pragma unroll 8
    for (int e = 0; e < EE; e++) acc += s[e] * Wemb[e * FF + f];
    g_Wc[g * FF + f] = acc;
    if (f == 0) {
        float bb = 0.f;
        for (int e = 0; e < EE; e++) bb += s[e] * bemb[e];
        g_biasc[g] = bb + bih[g] + bhh[g];
    }
}

// ---------------- 2. xg = x @ Wc^T + biasc, out [t][blk][c=jj*4+gate][b(32)] --
__global__ __launch_bounds__(256) void xg_kernel(const float* __restrict__ x) {
    __shared__ __align__(16) float xs[FF][68];
    __shared__ __align__(16) float ws[FF][68];
    int tb = blockIdx.x, cbase = blockIdx.y * 64, tid = threadIdx.x;
#pragma unroll
    for (int i = 0; i < 16; i++) {
        int idx = i * 256 + tid;
        int r = idx >> 6, k = idx & 63;
        xs[k][r] = x[((size_t)r * TT + tb) * FF + k];
        ws[k][r] = g_Wc[(size_t)(cbase + r) * FF + k];
    }
    __syncthreads();
    int rg = tid & 15, cg = tid >> 4;
    int r0 = rg * 4, c0 = cg * 4;
    unsigned long long acc[4][2] = {};
#pragma unroll 4
    for (int k = 0; k < FF; k++) {
        float4 hv = *(const float4*)&xs[k][r0];
        ulonglong2 wv = *(const ulonglong2*)&ws[k][c0];
        unsigned long long h0 = dup2(hv.x), h1 = dup2(hv.y), h2 = dup2(hv.z), h3 = dup2(hv.w);
        ffma2(acc[0][0], h0, wv.x); ffma2(acc[0][1], h0, wv.y);
        ffma2(acc[1][0], h1, wv.x); ffma2(acc[1][1], h1, wv.y);
        ffma2(acc[2][0], h2, wv.x); ffma2(acc[2][1], h2, wv.y);
        ffma2(acc[3][0], h3, wv.x); ffma2(acc[3][1], h3, wv.y);
    }
    int halfb = r0 >> 5;                      // batch half (float4 stays inside)
#pragma unroll
    for (int j = 0; j < 4; j++) {
        int g = cbase + c0 + j;
        float bias = g_biasc[g];
        int blk = halfb * 64 + ((g & 511) >> 3);
        int cc = ((g & 7) << 2) + (g >> 9);   // c = jj*4 + gate
        float4 v;
        v.x = ((j & 1) ? hi32(acc[0][j >> 1]) : lo32(acc[0][j >> 1])) + bias;
        v.y = ((j & 1) ? hi32(acc[1][j >> 1]) : lo32(acc[1][j >> 1])) + bias;
        v.z = ((j & 1) ? hi32(acc[2][j >> 1]) : lo32(acc[2][j >> 1])) + bias;
        v.w = ((j & 1) ? hi32(acc[3][j >> 1]) : lo32(acc[3][j >> 1])) + bias;
        *(float4*)&g_xg[((((size_t)tb * NBLK + blk) * 32 + cc) << 5) + (r0 & 31)] = v;
    }
}

// ---------------- 3. init ----------------
__global__ void init_state_kernel() {
    int i = blockIdx.x * 256 + threadIdx.x;
    if (i < 8192) ((uint4*)g_h16[0])[i] = make_uint4(0, 0, 0, 0);
    if (i < 16) g_cnt[i].v = 0u;
}

// ---------------- 4. persistent LSTM via mma.sync, warp-local epilogue -------
// 128 blocks x 256 threads. Block (bg = blk>>6, jg = blk&63): 32 batches x 8 units.
// 8 warps: mt = wid>>2 (16 batch rows), nt = wid&3 (8 cols = jj{2nt,2nt+1} x 4 gates).
// bf16 3-term split; epilogue entirely in-warp via one shfl.xor(1).
__global__ __launch_bounds__(256, 1) void lstm_mma(const float* __restrict__ Whh) {
    extern __shared__ __align__(16) unsigned char smem[];
    unsigned sb = smem_u32(smem);

    int tid = threadIdx.x, wid = tid >> 5, lane = tid & 31;
    int blk = blockIdx.x;
    int bg = blk >> 6, jg = blk & 63;
    int j0 = jg * 8, b0 = bg * 32;
    int mt = wid >> 2, nt = wid & 3;

    // one-time W conversion: smem row n = jj*4+gate, source row gate*512+j0+jj
    for (int idx = tid; idx < 32 * 512; idx += 256) {
        int k = idx & 511, n = idx >> 9;
        int jj = n >> 2, gate = n & 3;
        float w = Whh[(size_t)(gate * 512 + j0 + jj) * 512 + k];
        __nv_bfloat16 hb = __float2bfloat16(w);
        __nv_bfloat16 lb = __float2bfloat16(w - __bfloat162float(hb));
        *(unsigned short*)(smem + S_WHI + n * 1040 + k * 2) = *(unsigned short*)&hb;
        *(unsigned short*)(smem + S_WLO + n * 1040 + k * 2) = *(unsigned short*)&lb;
    }
    __syncthreads();

    // lane-fixed ldmatrix bases (frag layouts identical to R14/R16)
    int q = lane >> 3, r8 = lane & 7;
    unsigned aBase = sb + S_AHI + (unsigned)((mt * 16 + (q & 1) * 8 + r8) * 1040
                                             + ((q >> 1) * 8) * 2);
    unsigned bBase = sb + S_WHI + (unsigned)((nt * 8 + r8) * 1040
                                             + (((lane >> 3) & 1) * 8) * 2);

    // epilogue lane mapping: row/jj fixed per lane
    int tq = lane & 3;
    int brow = mt * 16 + (lane >> 2) + 8 * (tq & 1);   // local batch row
    int jj = 2 * nt + (tq >> 1);
    int hidx = (b0 + brow) * 512 + j0 + jj;

    float c_reg = 0.f, hsum_reg = 0.f;

    for (int t = 0; t < TT; t++) {
        // xg prefetch: 4 gates for this lane's (brow, jj)
        const float* xp = g_xg + (((size_t)t * NBLK + blk) << 10) + jj * 128 + brow;
        float xv0 = __ldcg(xp), xv1 = __ldcg(xp + 32), xv2 = __ldcg(xp + 64), xv3 = __ldcg(xp + 96);

        // A loads: warp wid owns local rows [wid*4, wid*4+4), hi+lo, 2 k-chunks
        const unsigned short* himg0 = g_h16[t & 1][0];
        const unsigned short* himg1 = g_h16[t & 1][1];
        int rbase = wid * 4;
#pragma unroll
        for (int g = 0; g < 2; g++) {
#pragma unroll
            for (int i = 0; i < 8; i++) {
                int e = i * 32 + lane;                 // 0..255
                int prec = e >> 7, e2 = e & 127;       // row(4) x kseg(32)
                int row = rbase + (e2 >> 5), kidx = e2 & 31;
                const unsigned short* src = (prec ? himg1 : himg0)
                                          + (b0 + row) * 512 + (g * 32 + kidx) * 8;
                cpasync16s(sb + S_AHI + prec * 33280u + row * 1040u
                           + (unsigned)(g * 32 + kidx) * 16u, src);
            }
            CP_COMMIT();
        }

        float d[4] = {0.f, 0.f, 0.f, 0.f};

#define CHUNK(KC, WN)                                                          \
        CP_WAITN(WN);                                                          \
        asm volatile("bar.sync %0, 128;" :: "r"(1 + mt) : "memory");           \
        {                                                                      \
            _Pragma("unroll")                                                  \
            for (int s = 0; s < 16; s++) {                                     \
                unsigned koff = (unsigned)(((KC) * 256 + s * 16) * 2);         \
                unsigned ah0, ah1, ah2, ah3, al0, al1, al2, al3;               \
                unsigned bh0, bh1, bl0, bl1;                                   \
                ldsm_x4(ah0, ah1, ah2, ah3, aBase + koff);                     \
                ldsm_x4(al0, al1, al2, al3, aBase + 33280u + koff);            \
                ldsm_x2(bh0, bh1, bBase + koff);                               \
                ldsm_x2(bl0, bl1, bBase + 33280u + koff);                      \
                mma16816(d, ah0, ah1, ah2, ah3, bh0, bh1);                     \
                mma16816(d, al0, al1, al2, al3, bh0, bh1);                     \
                mma16816(d, ah0, ah1, ah2, ah3, bl0, bl1);                     \
            }                                                                  \
        }
        CHUNK(0, 1)
        CHUNK(1, 0)
#undef CHUNK

        // warp-local epilogue: exchange gate pairs with adjacent lane
        float e0 = __shfl_xor_sync(0xffffffffu, d[0], 1);
        float e1 = __shfl_xor_sync(0xffffffffu, d[1], 1);
        float e2 = __shfl_xor_sync(0xffffffffu, d[2], 1);
        float e3 = __shfl_xor_sync(0xffffffffu, d[3], 1);
        float gi, gf, gg, go;
        if ((tq & 1) == 0) { gi = d[0]; gf = d[1]; gg = e0; go = e1; }   // row q
        else               { gi = e2; gf = e3; gg = d[2]; go = d[3]; }   // row q+8

        float iv = fsig(gi + xv0);
        float fv = fsig(gf + xv1);
        float gv = ftanh(gg + xv2);
        float ov = fsig(go + xv3);
        c_reg = fv * c_reg + iv * gv;
        float hn = ov * ftanh(c_reg);
        hsum_reg += hn;
        __nv_bfloat16 hb = __float2bfloat16(hn);
        __nv_bfloat16 lb = __float2bfloat16(hn - __bfloat162float(hb));
        int nbuf = (t + 1) & 1;
        g_h16[nbuf][0][hidx] = *(unsigned short*)&hb;
        g_h16[nbuf][1][hidx] = *(unsigned short*)&lb;

        // per-half grid barrier: 64 arrivals over 8 counters
        if (t < TT - 1) {
            __threadfence();
            __syncthreads();
            if (tid == 0) atomicAdd(&g_cnt[bg * 8 + (blk & 7)].v, 1u);
            if (tid < 8) {
                unsigned want = 8u * (unsigned)(t + 1);
                while (*(volatile unsigned*)&g_cnt[bg * 8 + tid].v < want) { }
            }
            __syncthreads();
            __threadfence();
        }
    }
    g_hsum[(b0 + brow) * HH + j0 + jj] = hsum_reg;
}

// ---------------- 5. pool + FC ----------------
__global__ void pool_fc_kernel(const float* __restrict__ Wfc,
                               const float* __restrict__ bfc,
                               float* __restrict__ out) {
    int b = blockIdx.x;
    __shared__ float sh[HH];
    int tid = threadIdx.x;
    for (int k = tid; k < HH; k += 256) sh[k] = g_hsum[b * HH + k];
    __syncthreads();
    int warp = tid >> 5, lane = tid & 31;
    for (int o = warp; o < OO; o += 8) {
        float a = 0.f;
        for (int k = lane; k < HH; k += 32) a += sh[k] * Wfc[o * HH + k];
#pragma unroll
        for (int s = 16; s; s >>= 1) a += __shfl_xor_sync(0xffffffffu, a, s);
        if (lane == 0) out[b * OO + o] = a * (1.f / 512.f) + bfc[o];
    }
}

extern "C" void kernel_launch(void* const* d_in, const int* in_sizes, int n_in,
                              void* d_out, int out_size) {
    const float* x    = (const float*)d_in[0];
    const float* Wemb = (const float*)d_in[1];
    const float* bemb = (const float*)d_in[2];
    const float* Wih  = (const float*)d_in[3];
    const float* Whh  = (const float*)d_in[4];
    const float* bih  = (const float*)d_in[5];
    const float* bhh  = (const float*)d_in[6];
    const float* Wfc  = (const float*)d_in[7];
    const float* bfc  = (const float*)d_in[8];
    float* out = (float*)d_out;

    static bool attr_set = false;
    if (!attr_set) {
        cudaFuncSetAttribute(lstm_mma, cudaFuncAttributeMaxDynamicSharedMemorySize, S_TOT);
        attr_set = true;
    }

    fuse_weights_kernel<<<GG, 64>>>(Wih, Wemb, bemb, bih, bhh);

    dim3 xgrid(TT, GG / 64);
    xg_kernel<<<xgrid, 256>>>(x);

    init_state_kernel<<<32, 256>>>();

    lstm_mma<<<NBLK, 256, S_TOT>>>(Whh);

    pool_fc_kernel<<<BB, 256>>>(Wfc, bfc, out);
}